// round 14
// baseline (speedup 1.0000x reference)
#include <cuda_runtime.h>
#include <cstdint>

// Problem constants (fixed shapes: B=4, C=8, H=W=1024, fp32)
static constexpr int B_  = 4;
static constexpr int C_  = 8;
static constexpr int HW_ = 1024 * 1024;      // positions per (b,c) plane

// Pipeline geometry: 4 blocks/SM, each a private 3-stage bulk-async pipeline.
// Smaller, more numerous independent pipelines -> smoother aggregate DRAM demand.
static constexpr int THREADS      = 128;
static constexpr int BLOCKS       = 152 * 4;             // 4 persistent blocks per SM
static constexpr int CHUNK        = 256;                 // spatial positions per stage
static constexpr int PLANES       = 2 * C_;              // 8 classes x {outs,targets}
static constexpr int PLANE_BYTES  = CHUNK * 4;           // 1024 B per plane slice
static constexpr int STAGE_BYTES  = PLANES * PLANE_BYTES; // 16 KB
static constexpr int STAGES       = 3;                   // 48 KB data / block
static constexpr int CH_PER_B     = HW_ / CHUNK;         // 4096 chunks per batch
static constexpr int NCHUNK       = B_ * CH_PER_B;       // 16384 chunks total

static constexpr int SMEM_MBAR  = 0;                     // 3 x 8B mbarriers
static constexpr int SMEM_DATA  = 1024;
static constexpr int SMEM_TOTAL = SMEM_DATA + STAGES * STAGE_BYTES;  // 50176 B -> 4 blocks/SM

// Scratch state (no device allocation -> __device__ globals; self-resetting).
__device__ double       g_partial /* = 0.0 */;
__device__ unsigned int g_count   /* = 0   */;

__device__ __forceinline__ uint32_t smem_u32(const void* p) {
    uint32_t a;
    asm("{ .reg .u64 t; cvta.to.shared.u64 t, %1; cvt.u32.u64 %0, t; }" : "=r"(a) : "l"(p));
    return a;
}
__device__ __forceinline__ void mbar_init(uint32_t mbar, uint32_t count) {
    asm volatile("mbarrier.init.shared.b64 [%0], %1;" :: "r"(mbar), "r"(count) : "memory");
}
__device__ __forceinline__ void mbar_expect_tx(uint32_t mbar, uint32_t bytes) {
    asm volatile("mbarrier.arrive.expect_tx.shared.b64 _, [%0], %1;"
                 :: "r"(mbar), "r"(bytes) : "memory");
}
__device__ __forceinline__ void mbar_wait(uint32_t mbar, uint32_t parity) {
    uint32_t done;
    asm volatile(
        "{\n\t.reg .pred p;\n\t"
        "mbarrier.try_wait.parity.acquire.cta.shared::cta.b64 p, [%1], %2;\n\t"
        "selp.b32 %0, 1, 0, p;\n\t}"
        : "=r"(done) : "r"(mbar), "r"(parity) : "memory");
    if (!done) {
        asm volatile(
            "{\n\t.reg .pred P1;\n\t"
            "W_%=:\n\t"
            "mbarrier.try_wait.parity.acquire.cta.shared::cta.b64 P1, [%0], %1, 0x989680;\n\t"
            "@P1 bra.uni D_%=;\n\t"
            "bra.uni W_%=;\n\t"
            "D_%=:\n\t}"
            :: "r"(mbar), "r"(parity) : "memory");
    }
}
__device__ __forceinline__ void bulk_g2s(uint32_t dst, const void* src,
                                         uint32_t bytes, uint32_t mbar) {
    asm volatile(
        "cp.async.bulk.shared::cta.global.mbarrier::complete_tx::bytes [%0], [%1], %2, [%3];"
        :: "r"(dst), "l"(src), "r"(bytes), "r"(mbar) : "memory");
}

// Issue all 16 bulk copies for chunk q into the given stage buffer.
__device__ __forceinline__ void issue_chunk(uint32_t data_base, uint32_t mbar,
                                            const float* __restrict__ outs,
                                            const float* __restrict__ targets,
                                            int q) {
    const int b  = q >> 12;                   // q / CH_PER_B (4096 = 2^12)
    const int s0 = (q & (CH_PER_B - 1)) << 8; // spatial float offset (x256)
    const float* ob = outs    + (size_t)b * (C_ * HW_) + s0;
    const float* tb = targets + (size_t)b * (C_ * HW_) + s0;
    mbar_expect_tx(mbar, STAGE_BYTES);
#pragma unroll
    for (int c = 0; c < C_; ++c) {
        bulk_g2s(data_base + c        * PLANE_BYTES, ob + (size_t)c * HW_, PLANE_BYTES, mbar);
        bulk_g2s(data_base + (C_ + c) * PLANE_BYTES, tb + (size_t)c * HW_, PLANE_BYTES, mbar);
    }
}

__global__ __launch_bounds__(THREADS, 4) void ce_tma_kernel(
    const float* __restrict__ outs,
    const float* __restrict__ targets,
    const float* __restrict__ cw,
    const int*   __restrict__ logits_flag,   // may be nullptr -> treat as 1
    float*       __restrict__ out)
{
    extern __shared__ char smem[];
    const uint32_t sbase = smem_u32(smem);
    const int tid = threadIdx.x;

    const bool do_ls = (logits_flag == nullptr) || (*logits_flag != 0);

    float w[C_];
#pragma unroll
    for (int c = 0; c < C_; ++c) w[c] = __ldg(&cw[c]);

    if (tid == 0) {
#pragma unroll
        for (int s = 0; s < STAGES; ++s) mbar_init(sbase + SMEM_MBAR + s * 8, 1);
    }
    __syncthreads();

    const int myChunks = (NCHUNK - (int)blockIdx.x + BLOCKS - 1) / BLOCKS;

    // Prologue: fill the pipeline
    if (tid == 0) {
        const int pre = myChunks < STAGES ? myChunks : STAGES;
        for (int k = 0; k < pre; ++k)
            issue_chunk(sbase + SMEM_DATA + k * STAGE_BYTES,
                        sbase + SMEM_MBAR + k * 8,
                        outs, targets, blockIdx.x + k * BLOCKS);
    }

    double accd = 0.0;

    for (int it = 0; it < myChunks; ++it) {
        const int      stage = it % STAGES;
        const uint32_t ph    = (uint32_t)((it / STAGES) & 1);
        mbar_wait(sbase + SMEM_MBAR + stage * 8, ph);

        // Phase 1: drain stage into registers (16x LDS.64), then release the
        // stage immediately so the refill overlaps the math.
        const float2* sp = reinterpret_cast<const float2*>(
            smem + SMEM_DATA + (size_t)stage * STAGE_BYTES);

        float2 o2[C_], t2[C_];
#pragma unroll
        for (int c = 0; c < C_; ++c) o2[c] = sp[c        * (CHUNK / 2) + tid];
#pragma unroll
        for (int c = 0; c < C_; ++c) t2[c] = sp[(C_ + c) * (CHUNK / 2) + tid];

        __syncthreads();   // all warps done reading -> stage is free
        if (tid == 0 && it + STAGES < myChunks)
            issue_chunk(sbase + SMEM_DATA + stage * STAGE_BYTES,
                        sbase + SMEM_MBAR + stage * 8,
                        outs, targets, blockIdx.x + (it + STAGES) * BLOCKS);

        // Phase 2: math (overlaps the in-flight refills).
        float sex = 0.f, sey = 0.f;
        float s1x = 0.f, s1y = 0.f;
        float s2x = 0.f, s2y = 0.f;
#pragma unroll
        for (int c = 0; c < C_; ++c) {
            const float wc = w[c];
            if (do_ls) {
                sex += __expf(o2[c].x);
                sey += __expf(o2[c].y);
            }
            float p;
            p = wc * t2[c].x; s1x = fmaf(p, o2[c].x, s1x); s2x += p;
            p = wc * t2[c].y; s1y = fmaf(p, o2[c].y, s1y); s2y += p;
        }

        float acc;
        if (do_ls) {
            acc = (s1x - __logf(sex) * s2x) + (s1y - __logf(sey) * s2y);
        } else {
            acc = s1x + s1y;
        }
        accd += (double)acc;
    }

    // Block reduction in double, one atomicAdd per block (608 total).
    double v = accd;
#pragma unroll
    for (int off = 16; off > 0; off >>= 1)
        v += __shfl_down_sync(0xffffffffu, v, off);

    __shared__ double rsm[THREADS / 32];
    __shared__ bool   s_last;
    const int lane = tid & 31;
    const int wid  = tid >> 5;
    if (lane == 0) rsm[wid] = v;
    if (tid == 0) s_last = false;
    __syncthreads();

    if (wid == 0) {
        double bv = (lane < THREADS / 32) ? rsm[lane] : 0.0;
#pragma unroll
        for (int off = 4; off > 0; off >>= 1)
            bv += __shfl_down_sync(0xffffffffu, bv, off);
        if (lane == 0) {
            atomicAdd(&g_partial, bv);
            __threadfence();
            unsigned prev = atomicInc(&g_count, gridDim.x - 1);  // self-resetting
            s_last = (prev == gridDim.x - 1);
        }
    }
    __syncthreads();

    // Last block: read total AND reset to 0.0 in one atomic, write output.
    if (s_last && tid == 0) {
        double total = __longlong_as_double(
            atomicExch(reinterpret_cast<unsigned long long*>(&g_partial), 0ULL));
        out[0] = (float)(-total / ((double)B_ * (double)C_ * (double)HW_));
    }
}

extern "C" void kernel_launch(void* const* d_in, const int* in_sizes, int n_in,
                              void* d_out, int out_size)
{
    const float* outs    = (const float*)d_in[0];
    const float* targets = (const float*)d_in[1];
    const float* cw      = (const float*)d_in[2];
    const int*   flag    = (n_in >= 4) ? (const int*)d_in[3] : nullptr;
    float* out = (float*)d_out;

    static bool attr_set = false;
    if (!attr_set) {
        cudaFuncSetAttribute(ce_tma_kernel,
                             cudaFuncAttributeMaxDynamicSharedMemorySize, SMEM_TOTAL);
        attr_set = true;
    }

    ce_tma_kernel<<<BLOCKS, THREADS, SMEM_TOTAL>>>(outs, targets, cw, flag, out);
}